// round 11
// baseline (speedup 1.0000x reference)
#include <cuda_runtime.h>
#include <math.h>
#include <stdint.h>

#define NN   100000
#define FN   2
#define FE   7
#define NH   4
#define HC   32
#define EMAX 3200000
#define REGF 500

#define CP_ASYNC16(dst, src) \
    asm volatile("cp.async.cg.shared.global [%0], [%1], 16;" :: "r"(dst), "l"(src) : "memory")
#define CP_COMMIT() asm volatile("cp.async.commit_group;" ::: "memory")
#define CP_WAIT1()  asm volatile("cp.async.wait_group 1;" ::: "memory")

__device__ __forceinline__ uint32_t smem_u32(const void* p) {
    uint32_t a;
    asm("{ .reg .u64 t; cvta.to.shared.u64 t, %1; cvt.u32.u64 %0, t; }" : "=r"(a) : "l"(p));
    return a;
}

// ---------------- scratch (static device globals; no runtime alloc) ----------------
__device__ float g_xl[(size_t)NN * HC];
__device__ float g_xr[(size_t)NN * HC];
__device__ float g_h1[(size_t)NN * HC];
__device__ float g_h2[(size_t)NN * HC];
__device__ __align__(16) int g_cnt[NN];   // zero at load; scan re-zeros after reading
__device__ int   g_rowptr[NN + 1];
__device__ int   g_cur[NN];
__device__ __align__(16) float g_pedge[(size_t)EMAX * 8 + 8];  // 32B rec: [0..6]=ea, [7]=src (+pad)
__device__ float g_eamean[FE];
__device__ float g_stats[2 * HC];
__device__ float g_ab[2 * HC];
__device__ float g_weff[HC + 1];

__device__ __forceinline__ float lrelu(float x, float s) { return fmaxf(x, s * x); }

// ---------------- fused: transform layer-1 (node blocks) + degree hist (edge blocks) ----
__global__ void t1_hist_kernel(const float* __restrict__ x,
                               const float* __restrict__ Wl, const float* __restrict__ bl,
                               const float* __restrict__ Wr, const float* __restrict__ br,
                               int n, const int* __restrict__ eidx, int E, int nbN) {
    if ((int)blockIdx.x >= nbN) {  // histogram part
        int e = (blockIdx.x - nbN) * blockDim.x + threadIdx.x;
        if (e < E) atomicAdd(&g_cnt[eidx[E + e]], 1);
        return;
    }
    __shared__ float sWl[FN * HC], sWr[FN * HC], sb[2 * HC];
    for (int t = threadIdx.x; t < FN * HC; t += blockDim.x) { sWl[t] = Wl[t]; sWr[t] = Wr[t]; }
    for (int t = threadIdx.x; t < HC; t += blockDim.x) { sb[t] = bl[t]; sb[HC + t] = br[t]; }
    if (blockIdx.x == 0 && threadIdx.x < 2 * HC) g_stats[threadIdx.x] = 0.f;
    __syncthreads();
    int i = blockIdx.x * blockDim.x + threadIdx.x;
    if (i >= n) return;
    float in0 = x[(size_t)i * FN], in1 = x[(size_t)i * FN + 1];
    float vl[HC], vr[HC];
#pragma unroll
    for (int c = 0; c < HC; c++) {
        vl[c] = sb[c] + in0 * sWl[c] + in1 * sWl[HC + c];
        vr[c] = sb[HC + c] + in0 * sWr[c] + in1 * sWr[HC + c];
    }
    float4* pl = (float4*)(g_xl + (size_t)i * HC);
    float4* pr = (float4*)(g_xr + (size_t)i * HC);
#pragma unroll
    for (int q = 0; q < 8; q++) {
        pl[q] = make_float4(vl[q * 4], vl[q * 4 + 1], vl[q * 4 + 2], vl[q * 4 + 3]);
        pr[q] = make_float4(vr[q * 4], vr[q * 4 + 1], vr[q * 4 + 2], vr[q * 4 + 3]);
    }
}

// single-block scan; zeros g_eamean; re-zeros g_cnt after reading (replay-safe)
__global__ void scan_kernel(int n) {
    __shared__ int a[1024];
    int t = threadIdx.x;
    if (t < FE) g_eamean[t] = 0.f;
    const int chunk = 100;
    int lo = t * chunk;
    int hi = lo + chunk; if (hi > n) hi = n; if (lo > n) lo = n;
    int s = 0;
    for (int i = lo; i < hi; i++) s += g_cnt[i];
    a[t] = s;
    __syncthreads();
    for (int off = 1; off < 1024; off <<= 1) {
        int u = (t >= off) ? a[t - off] : 0;
        __syncthreads();
        a[t] += u;
        __syncthreads();
    }
    int run = a[t] - s;
    for (int i = lo; i < hi; i++) {
        int c = g_cnt[i];
        g_cnt[i] = 0;
        g_rowptr[i] = run;
        g_cur[i] = run;
        run += c;
    }
    if (t == 1023) g_rowptr[n] = a[1023];
}

// scatter edges into CSR order (32B record); accumulates ea sums
__global__ void scatter_kernel(const int* __restrict__ eidx, const float* __restrict__ ea, int E) {
    __shared__ float sh[FE];
    if (threadIdx.x < FE) sh[threadIdx.x] = 0.f;
    __syncthreads();
    int e = blockIdx.x * blockDim.x + threadIdx.x;
    float v[FE];
    if (e < E) {
        int s = eidx[e];
        int d = eidx[E + e];
#pragma unroll
        for (int k = 0; k < FE; k++) v[k] = ea[(size_t)e * FE + k];
        int pos = atomicAdd(&g_cur[d], 1);
        float4* rec = (float4*)(g_pedge + (size_t)pos * 8);
        rec[0] = make_float4(v[0], v[1], v[2], v[3]);
        rec[1] = make_float4(v[4], v[5], v[6], __int_as_float(s));
    } else {
#pragma unroll
        for (int k = 0; k < FE; k++) v[k] = 0.f;
    }
#pragma unroll
    for (int k = 0; k < FE; k++) {
        float x = v[k];
#pragma unroll
        for (int o = 16; o > 0; o >>= 1) x += __shfl_down_sync(0xffffffffu, x, o);
        if ((threadIdx.x & 31) == 0) atomicAdd(&sh[k], x);
    }
    __syncthreads();
    if (threadIdx.x < FE) atomicAdd(&g_eamean[threadIdx.x], sh[threadIdx.x]);
}

// parallel weff
__global__ void weff_kernel(const float* __restrict__ Wreg, const float* __restrict__ breg,
                            const float* __restrict__ Wend, const float* __restrict__ bend) {
    int w = threadIdx.x >> 5, lane = threadIdx.x & 31;
    float s = 0.f;
    for (int r = lane; r < REGF; r += 32) s += Wreg[w * REGF + r] * Wend[r];
#pragma unroll
    for (int o = 16; o > 0; o >>= 1) s += __shfl_down_sync(0xffffffffu, s, o);
    if (lane == 0) g_weff[w] = s;
    if (w == 0) {
        float b = 0.f;
        for (int r = lane; r < REGF; r += 32) b += breg[r] * Wend[r];
#pragma unroll
        for (int o = 16; o > 0; o >>= 1) b += __shfl_down_sync(0xffffffffu, b, o);
        if (lane == 0) g_weff[HC] = b + bend[0];
    }
}

// ---- node transform for layers 2/3 (F=HC, BN+act fused) ----
__global__ void transform_kernel(int insel,
                                 const float* __restrict__ Wl, const float* __restrict__ bl,
                                 const float* __restrict__ Wr, const float* __restrict__ br,
                                 int n) {
    __shared__ float sWl[HC * HC], sWr[HC * HC], sb[2 * HC];
    for (int t = threadIdx.x; t < HC * HC; t += blockDim.x) { sWl[t] = Wl[t]; sWr[t] = Wr[t]; }
    for (int t = threadIdx.x; t < HC; t += blockDim.x) { sb[t] = bl[t]; sb[HC + t] = br[t]; }
    if (blockIdx.x == 0 && threadIdx.x < 2 * HC) g_stats[threadIdx.x] = 0.f;
    __syncthreads();
    int i = blockIdx.x * blockDim.x + threadIdx.x;
    if (i >= n) return;
    const float* hin = insel ? g_h2 : g_h1;

    float in[HC];
#pragma unroll
    for (int k = 0; k < HC; k++) {
        float v = hin[(size_t)i * HC + k];
        v = v * g_ab[k] + g_ab[HC + k];
        in[k] = lrelu(v, 0.01f);
    }
    float vl[HC], vr[HC];
#pragma unroll
    for (int c = 0; c < HC; c++) { vl[c] = sb[c]; vr[c] = sb[HC + c]; }
#pragma unroll
    for (int k = 0; k < HC; k++) {
        float a = in[k];
#pragma unroll
        for (int c = 0; c < HC; c++) { vl[c] += a * sWl[k * HC + c]; vr[c] += a * sWr[k * HC + c]; }
    }
    float4* pl = (float4*)(g_xl + (size_t)i * HC);
    float4* pr = (float4*)(g_xr + (size_t)i * HC);
#pragma unroll
    for (int q = 0; q < 8; q++) {
        pl[q] = make_float4(vl[q * 4], vl[q * 4 + 1], vl[q * 4 + 2], vl[q * 4 + 3]);
        pr[q] = make_float4(vr[q * 4], vr[q * 4 + 1], vr[q * 4 + 2], vr[q * 4 + 3]);
    }
}

// ---------------- warp-per-node GATv2 aggregation: cp.async ring + 1-iter xl prefetch ---
// group g = lane>>3 owns one edge per iteration; cs = lane&7 owns channels [cs*4,cs*4+4).
// Records stream DRAM->smem via cp.async (3-slot ring, fill(j+2) then wait_group 1 so
// rounds j AND j+1 are readable in round j). Each iteration reads iteration t+1's record
// from smem and issues its xl LDG before computing iteration t -> gather latency hidden.
template <int MODE>
__global__ void __launch_bounds__(256, 2)
gat_aggr_kernel(const float* __restrict__ We, const float* __restrict__ att,
                const float* __restrict__ bias, float invE, int n, int hsel,
                float* __restrict__ out) {
    __shared__ __align__(16) char ringbuf[8 * 3 * 512];  // 8 warps x 3 rounds x 512B
    __shared__ float sWem[HC];   // ee_mean = (mean ea) @ We
    __shared__ float sb[HC];
    __shared__ float swf[HC + 1];
    __shared__ float sst[2 * HC];
    int t = threadIdx.x;
    if (t < HC) {
        sb[t] = bias[t];
        float s = 0.f;
#pragma unroll
        for (int k = 0; k < FE; k++) s += g_eamean[k] * invE * We[k * HC + t];
        sWem[t] = s;
    }
    if (MODE == 0 && t < 2 * HC) sst[t] = 0.f;
    if (MODE == 1 && t < HC + 1) swf[t] = g_weff[t];
    __syncthreads();

    const unsigned FULL = 0xffffffffu;
    int lane = threadIdx.x & 31;
    int warpid = threadIdx.x >> 5;
    int g = lane >> 3, cs = lane & 7;

    float4 wk[FE];
#pragma unroll
    for (int k = 0; k < FE; k++) wk[k] = *(const float4*)(We + k * HC + cs * 4);
    float4 att4 = *(const float4*)(att + cs * 4);

    int i = (blockIdx.x * blockDim.x + threadIdx.x) >> 5;
    if (i < n) {
        int r0 = g_rowptr[i];
        int deg = g_rowptr[i + 1] - r0;
        float4 xr4 = *(const float4*)(g_xr + (size_t)i * HC + cs * 4);
        float4 acc = make_float4(0.f, 0.f, 0.f, 0.f);
        float den = 0.f;

        const char* peb = (const char*)g_pedge + (size_t)r0 * 32;
        char* ringw = ringbuf + warpid * 1536;
        uint32_t ru32 = smem_u32(ringw);

        int nit = (deg + 3) >> 2;       // iterations of 4 edges
        int nrounds = (nit + 3) >> 2;   // rounds of 16 records

        auto fill = [&](int j) {
            int r = j * 16 + (lane >> 1);
            int rc = (r < deg) ? r : 0;
            uint32_t dst = ru32 + (uint32_t)(j % 3) * 512u + (uint32_t)lane * 16u;
            CP_ASYNC16(dst, peb + (size_t)rc * 32 + (lane & 1) * 16);
            CP_COMMIT();
        };
        fill(0);
        fill(1);

        float4 na0, na1, nxl;
        int it = 0;
        for (int j = 0; j < nrounds; j++) {
            fill(j + 2);
            CP_WAIT1();       // rounds j and j+1 now resident
            __syncwarp();
            if (j == 0) {     // prologue: prefetch iteration 0
                const char* rp = ringw + g * 32;
                na0 = *(const float4*)rp;
                na1 = *(const float4*)(rp + 16);
                int s0 = (g < deg) ? __float_as_int(na1.w) : i;
                nxl = *(const float4*)(g_xl + (size_t)s0 * HC + cs * 4);
            }
            int tmax = nit - j * 4; if (tmax > 4) tmax = 4;
            for (int tt = 0; tt < tmax; tt++, it++) {
                float4 a0 = na0, a1 = na1, xl4 = nxl;
                bool valid = (it * 4 + g) < deg;

                // prefetch iteration it+1 (record from smem, xl LDG)
                int nt = (it + 1 < nit) ? it + 1 : it;
                const char* np = ringw + ((nt >> 2) % 3) * 512 + (((nt & 3) * 4 + g) << 5);
                na0 = *(const float4*)np;
                na1 = *(const float4*)(np + 16);
                int ns = ((it + 1) * 4 + g < deg) ? __float_as_int(na1.w) : i;
                nxl = *(const float4*)(g_xl + (size_t)ns * HC + cs * 4);

                // compute iteration it (all operands resident)
                float e0 = fmaf(a0.x, wk[0].x, xr4.x);
                float e1 = fmaf(a0.x, wk[0].y, xr4.y);
                float e2 = fmaf(a0.x, wk[0].z, xr4.z);
                float e3 = fmaf(a0.x, wk[0].w, xr4.w);
                e0 = fmaf(a0.y, wk[1].x, e0); e1 = fmaf(a0.y, wk[1].y, e1);
                e2 = fmaf(a0.y, wk[1].z, e2); e3 = fmaf(a0.y, wk[1].w, e3);
                e0 = fmaf(a0.z, wk[2].x, e0); e1 = fmaf(a0.z, wk[2].y, e1);
                e2 = fmaf(a0.z, wk[2].z, e2); e3 = fmaf(a0.z, wk[2].w, e3);
                e0 = fmaf(a0.w, wk[3].x, e0); e1 = fmaf(a0.w, wk[3].y, e1);
                e2 = fmaf(a0.w, wk[3].z, e2); e3 = fmaf(a0.w, wk[3].w, e3);
                e0 = fmaf(a1.x, wk[4].x, e0); e1 = fmaf(a1.x, wk[4].y, e1);
                e2 = fmaf(a1.x, wk[4].z, e2); e3 = fmaf(a1.x, wk[4].w, e3);
                e0 = fmaf(a1.y, wk[5].x, e0); e1 = fmaf(a1.y, wk[5].y, e1);
                e2 = fmaf(a1.y, wk[5].z, e2); e3 = fmaf(a1.y, wk[5].w, e3);
                e0 = fmaf(a1.z, wk[6].x, e0); e1 = fmaf(a1.z, wk[6].y, e1);
                e2 = fmaf(a1.z, wk[6].z, e2); e3 = fmaf(a1.z, wk[6].w, e3);

                float m0 = lrelu(xl4.x + e0, 0.2f);
                float m1 = lrelu(xl4.y + e1, 0.2f);
                float m2 = lrelu(xl4.z + e2, 0.2f);
                float m3 = lrelu(xl4.w + e3, 0.2f);
                float pl = fmaf(m0, att4.x, fmaf(m1, att4.y, fmaf(m2, att4.z, m3 * att4.w)));
                float lg = pl + __shfl_xor_sync(FULL, pl, 1);
                float ex = valid ? __expf(lg) : 0.f;
                den += ex;
                acc.x = fmaf(ex, xl4.x, acc.x);
                acc.y = fmaf(ex, xl4.y, acc.y);
                acc.z = fmaf(ex, xl4.z, acc.z);
                acc.w = fmaf(ex, xl4.w, acc.w);
            }
        }

        // self-loop contribution (ea = mean): all lanes compute; group 0 accumulates
        {
            float4 xli = *(const float4*)(g_xl + (size_t)i * HC + cs * 4);
            float m0 = lrelu(xli.x + xr4.x + sWem[cs * 4 + 0], 0.2f);
            float m1 = lrelu(xli.y + xr4.y + sWem[cs * 4 + 1], 0.2f);
            float m2 = lrelu(xli.z + xr4.z + sWem[cs * 4 + 2], 0.2f);
            float m3 = lrelu(xli.w + xr4.w + sWem[cs * 4 + 3], 0.2f);
            float pl = fmaf(m0, att4.x, fmaf(m1, att4.y, fmaf(m2, att4.z, m3 * att4.w)));
            float lg = pl + __shfl_xor_sync(FULL, pl, 1);
            float ex = __expf(lg);
            if (g == 0) {
                den += ex;
                acc.x = fmaf(ex, xli.x, acc.x);
                acc.y = fmaf(ex, xli.y, acc.y);
                acc.z = fmaf(ex, xli.z, acc.z);
                acc.w = fmaf(ex, xli.w, acc.w);
            }
        }

#pragma unroll
        for (int off = 8; off < 32; off <<= 1) {
            acc.x += __shfl_xor_sync(FULL, acc.x, off);
            acc.y += __shfl_xor_sync(FULL, acc.y, off);
            acc.z += __shfl_xor_sync(FULL, acc.z, off);
            acc.w += __shfl_xor_sync(FULL, acc.w, off);
            den   += __shfl_xor_sync(FULL, den,   off);
        }
        if (g == 0) {
            float inv = 1.f / (den + 1e-16f);
            float h0 = acc.x * inv + sb[cs * 4];
            float h1 = acc.y * inv + sb[cs * 4 + 1];
            float h2 = acc.z * inv + sb[cs * 4 + 2];
            float h3 = acc.w * inv + sb[cs * 4 + 3];
            if (MODE == 0) {
                float* hp = (hsel ? g_h2 : g_h1) + (size_t)i * HC + cs * 4;
                *(float4*)hp = make_float4(h0, h1, h2, h3);
                atomicAdd(&sst[cs * 4 + 0], h0);
                atomicAdd(&sst[cs * 4 + 1], h1);
                atomicAdd(&sst[cs * 4 + 2], h2);
                atomicAdd(&sst[cs * 4 + 3], h3);
                atomicAdd(&sst[HC + cs * 4 + 0], h0 * h0);
                atomicAdd(&sst[HC + cs * 4 + 1], h1 * h1);
                atomicAdd(&sst[HC + cs * 4 + 2], h2 * h2);
                atomicAdd(&sst[HC + cs * 4 + 3], h3 * h3);
            } else {
                float s = lrelu(h0, 0.01f) * swf[cs * 4]
                        + lrelu(h1, 0.01f) * swf[cs * 4 + 1]
                        + lrelu(h2, 0.01f) * swf[cs * 4 + 2]
                        + lrelu(h3, 0.01f) * swf[cs * 4 + 3];
                s += __shfl_xor_sync(0x000000ffu, s, 1);
                s += __shfl_xor_sync(0x000000ffu, s, 2);
                s += __shfl_xor_sync(0x000000ffu, s, 4);
                if (cs == 0) out[i] = s + swf[HC];
            }
        }
    }
    if (MODE == 0) {
        __syncthreads();
        if (t < 2 * HC) atomicAdd(&g_stats[t], sst[t]);
    }
}

__global__ void bn_finalize_kernel(const float* __restrict__ gamma,
                                   const float* __restrict__ beta, float invn) {
    int c = threadIdx.x;
    if (c >= HC) return;
    float mu = g_stats[c] * invn;
    float var = g_stats[HC + c] * invn - mu * mu;
    float A = rsqrtf(var + 1e-5f) * gamma[c];
    g_ab[c] = A;
    g_ab[HC + c] = beta[c] - mu * A;
}

// ---------------- launch ----------------
extern "C" void kernel_launch(void* const* d_in, const int* in_sizes, int n_in,
                              void* d_out, int out_size) {
    const float* x    = (const float*)d_in[0];
    const int*   eidx = (const int*)d_in[1];
    const float* ea   = (const float*)d_in[2];
    const float* Wl1 = (const float*)d_in[3];  const float* bl1 = (const float*)d_in[4];
    const float* Wr1 = (const float*)d_in[5];  const float* br1 = (const float*)d_in[6];
    const float* We1 = (const float*)d_in[7];  const float* att1 = (const float*)d_in[8];
    const float* b1  = (const float*)d_in[9];
    const float* Wl2 = (const float*)d_in[10]; const float* bl2 = (const float*)d_in[11];
    const float* Wr2 = (const float*)d_in[12]; const float* br2 = (const float*)d_in[13];
    const float* We2 = (const float*)d_in[14]; const float* att2 = (const float*)d_in[15];
    const float* b2  = (const float*)d_in[16];
    const float* gamma = (const float*)d_in[17]; const float* beta = (const float*)d_in[18];
    const float* Wreg = (const float*)d_in[19];  const float* breg = (const float*)d_in[20];
    const float* Wend = (const float*)d_in[21];  const float* bend = (const float*)d_in[22];
    float* out = (float*)d_out;

    int n = in_sizes[0] / FN;
    int E = in_sizes[1] / 2;
    float invE = 1.f / (float)E;
    int nbN = (n + 255) / 256;
    int nbE = (E + 255) / 256;
    int nbW = (n * 32 + 255) / 256;

    t1_hist_kernel<<<nbN + nbE, 256>>>(x, Wl1, bl1, Wr1, br1, n, eidx, E, nbN); // 0
    scan_kernel<<<1, 1024>>>(n);                                                // 1
    scatter_kernel<<<nbE, 256>>>(eidx, ea, E);                                  // 2
    gat_aggr_kernel<0><<<nbW, 256>>>(We1, att1, b1, invE, n, 0, nullptr);       // 3 <- profiled
    bn_finalize_kernel<<<1, 32>>>(gamma, beta, 1.f / (float)n);                 // 4

    transform_kernel<<<nbN, 256>>>(0, Wl2, bl2, Wr2, br2, n);                   // 5
    gat_aggr_kernel<0><<<nbW, 256>>>(We2, att2, b2, invE, n, 1, nullptr);       // 6
    bn_finalize_kernel<<<1, 32>>>(gamma, beta, 1.f / (float)n);                 // 7

    transform_kernel<<<nbN, 256>>>(1, Wl2, bl2, Wr2, br2, n);                   // 8
    weff_kernel<<<1, 1024>>>(Wreg, breg, Wend, bend);                           // 9
    gat_aggr_kernel<1><<<nbW, 256>>>(We2, att2, b2, invE, n, 0, out);           // 10
}

// round 12
// speedup vs baseline: 1.0776x; 1.0776x over previous
#include <cuda_runtime.h>
#include <math.h>
#include <stdint.h>

#define NN   100000
#define FN   2
#define FE   7
#define NH   4
#define HC   32
#define EMAX 3200000
#define REGF 500

#define CP_ASYNC16(dst, src) \
    asm volatile("cp.async.cg.shared.global [%0], [%1], 16;" :: "r"(dst), "l"(src) : "memory")
#define CP_COMMIT() asm volatile("cp.async.commit_group;" ::: "memory")
#define CP_WAIT1()  asm volatile("cp.async.wait_group 1;" ::: "memory")

__device__ __forceinline__ uint32_t smem_u32(const void* p) {
    uint32_t a;
    asm("{ .reg .u64 t; cvta.to.shared.u64 t, %1; cvt.u32.u64 %0, t; }" : "=r"(a) : "l"(p));
    return a;
}

// ---------------- scratch (static device globals; no runtime alloc) ----------------
__device__ float g_xl[(size_t)NN * HC];
__device__ float g_xr[(size_t)NN * HC];
__device__ float g_h1[(size_t)NN * HC];
__device__ float g_h2[(size_t)NN * HC];
__device__ __align__(16) int g_cnt[NN];   // zero at load; scan re-zeros after reading
__device__ int   g_rowptr[NN + 1];
__device__ int   g_cur[NN];
__device__ __align__(16) float g_pedge[(size_t)EMAX * 8 + 8];  // 32B rec: [0..6]=ea, [7]=src (+pad)
__device__ float g_eamean[FE];
__device__ float g_stats[2 * HC];
__device__ float g_ab[2 * HC];
__device__ float g_weff[HC + 1];

__device__ __forceinline__ float lrelu(float x, float s) { return fmaxf(x, s * x); }

// ---------------- fused: transform layer-1 (node blocks) + degree hist (edge blocks) ----
__global__ void t1_hist_kernel(const float* __restrict__ x,
                               const float* __restrict__ Wl, const float* __restrict__ bl,
                               const float* __restrict__ Wr, const float* __restrict__ br,
                               int n, const int* __restrict__ eidx, int E, int nbN) {
    if ((int)blockIdx.x >= nbN) {  // histogram part
        int e = (blockIdx.x - nbN) * blockDim.x + threadIdx.x;
        if (e < E) atomicAdd(&g_cnt[eidx[E + e]], 1);
        return;
    }
    __shared__ float sWl[FN * HC], sWr[FN * HC], sb[2 * HC];
    for (int t = threadIdx.x; t < FN * HC; t += blockDim.x) { sWl[t] = Wl[t]; sWr[t] = Wr[t]; }
    for (int t = threadIdx.x; t < HC; t += blockDim.x) { sb[t] = bl[t]; sb[HC + t] = br[t]; }
    if (blockIdx.x == 0 && threadIdx.x < 2 * HC) g_stats[threadIdx.x] = 0.f;
    __syncthreads();
    int i = blockIdx.x * blockDim.x + threadIdx.x;
    if (i >= n) return;
    float in0 = x[(size_t)i * FN], in1 = x[(size_t)i * FN + 1];
    float vl[HC], vr[HC];
#pragma unroll
    for (int c = 0; c < HC; c++) {
        vl[c] = sb[c] + in0 * sWl[c] + in1 * sWl[HC + c];
        vr[c] = sb[HC + c] + in0 * sWr[c] + in1 * sWr[HC + c];
    }
    float4* pl = (float4*)(g_xl + (size_t)i * HC);
    float4* pr = (float4*)(g_xr + (size_t)i * HC);
#pragma unroll
    for (int q = 0; q < 8; q++) {
        pl[q] = make_float4(vl[q * 4], vl[q * 4 + 1], vl[q * 4 + 2], vl[q * 4 + 3]);
        pr[q] = make_float4(vr[q * 4], vr[q * 4 + 1], vr[q * 4 + 2], vr[q * 4 + 3]);
    }
}

// single-block scan; zeros g_eamean; re-zeros g_cnt after reading (replay-safe)
__global__ void scan_kernel(int n) {
    __shared__ int a[1024];
    int t = threadIdx.x;
    if (t < FE) g_eamean[t] = 0.f;
    const int chunk = 100;
    int lo = t * chunk;
    int hi = lo + chunk; if (hi > n) hi = n; if (lo > n) lo = n;
    int s = 0;
    for (int i = lo; i < hi; i++) s += g_cnt[i];
    a[t] = s;
    __syncthreads();
    for (int off = 1; off < 1024; off <<= 1) {
        int u = (t >= off) ? a[t - off] : 0;
        __syncthreads();
        a[t] += u;
        __syncthreads();
    }
    int run = a[t] - s;
    for (int i = lo; i < hi; i++) {
        int c = g_cnt[i];
        g_cnt[i] = 0;
        g_rowptr[i] = run;
        g_cur[i] = run;
        run += c;
    }
    if (t == 1023) g_rowptr[n] = a[1023];
}

// scatter edges into CSR order (32B record); accumulates ea sums
__global__ void scatter_kernel(const int* __restrict__ eidx, const float* __restrict__ ea, int E) {
    __shared__ float sh[FE];
    if (threadIdx.x < FE) sh[threadIdx.x] = 0.f;
    __syncthreads();
    int e = blockIdx.x * blockDim.x + threadIdx.x;
    float v[FE];
    if (e < E) {
        int s = eidx[e];
        int d = eidx[E + e];
#pragma unroll
        for (int k = 0; k < FE; k++) v[k] = ea[(size_t)e * FE + k];
        int pos = atomicAdd(&g_cur[d], 1);
        float4* rec = (float4*)(g_pedge + (size_t)pos * 8);
        rec[0] = make_float4(v[0], v[1], v[2], v[3]);
        rec[1] = make_float4(v[4], v[5], v[6], __int_as_float(s));
    } else {
#pragma unroll
        for (int k = 0; k < FE; k++) v[k] = 0.f;
    }
#pragma unroll
    for (int k = 0; k < FE; k++) {
        float x = v[k];
#pragma unroll
        for (int o = 16; o > 0; o >>= 1) x += __shfl_down_sync(0xffffffffu, x, o);
        if ((threadIdx.x & 31) == 0) atomicAdd(&sh[k], x);
    }
    __syncthreads();
    if (threadIdx.x < FE) atomicAdd(&g_eamean[threadIdx.x], sh[threadIdx.x]);
}

// parallel weff
__global__ void weff_kernel(const float* __restrict__ Wreg, const float* __restrict__ breg,
                            const float* __restrict__ Wend, const float* __restrict__ bend) {
    int w = threadIdx.x >> 5, lane = threadIdx.x & 31;
    float s = 0.f;
    for (int r = lane; r < REGF; r += 32) s += Wreg[w * REGF + r] * Wend[r];
#pragma unroll
    for (int o = 16; o > 0; o >>= 1) s += __shfl_down_sync(0xffffffffu, s, o);
    if (lane == 0) g_weff[w] = s;
    if (w == 0) {
        float b = 0.f;
        for (int r = lane; r < REGF; r += 32) b += breg[r] * Wend[r];
#pragma unroll
        for (int o = 16; o > 0; o >>= 1) b += __shfl_down_sync(0xffffffffu, b, o);
        if (lane == 0) g_weff[HC] = b + bend[0];
    }
}

// ---- node transform for layers 2/3 (F=HC, BN+act fused) ----
__global__ void transform_kernel(int insel,
                                 const float* __restrict__ Wl, const float* __restrict__ bl,
                                 const float* __restrict__ Wr, const float* __restrict__ br,
                                 int n) {
    __shared__ float sWl[HC * HC], sWr[HC * HC], sb[2 * HC];
    for (int t = threadIdx.x; t < HC * HC; t += blockDim.x) { sWl[t] = Wl[t]; sWr[t] = Wr[t]; }
    for (int t = threadIdx.x; t < HC; t += blockDim.x) { sb[t] = bl[t]; sb[HC + t] = br[t]; }
    if (blockIdx.x == 0 && threadIdx.x < 2 * HC) g_stats[threadIdx.x] = 0.f;
    __syncthreads();
    int i = blockIdx.x * blockDim.x + threadIdx.x;
    if (i >= n) return;
    const float* hin = insel ? g_h2 : g_h1;

    float in[HC];
#pragma unroll
    for (int k = 0; k < HC; k++) {
        float v = hin[(size_t)i * HC + k];
        v = v * g_ab[k] + g_ab[HC + k];
        in[k] = lrelu(v, 0.01f);
    }
    float vl[HC], vr[HC];
#pragma unroll
    for (int c = 0; c < HC; c++) { vl[c] = sb[c]; vr[c] = sb[HC + c]; }
#pragma unroll
    for (int k = 0; k < HC; k++) {
        float a = in[k];
#pragma unroll
        for (int c = 0; c < HC; c++) { vl[c] += a * sWl[k * HC + c]; vr[c] += a * sWr[k * HC + c]; }
    }
    float4* pl = (float4*)(g_xl + (size_t)i * HC);
    float4* pr = (float4*)(g_xr + (size_t)i * HC);
#pragma unroll
    for (int q = 0; q < 8; q++) {
        pl[q] = make_float4(vl[q * 4], vl[q * 4 + 1], vl[q * 4 + 2], vl[q * 4 + 3]);
        pr[q] = make_float4(vr[q * 4], vr[q * 4 + 1], vr[q * 4 + 2], vr[q * 4 + 3]);
    }
}

// ---------------- warp-per-node GATv2: cp.async ring + round-batched xl gathers --------
// group g = lane>>3 owns one edge per iteration; cs = lane&7 owns channels [cs*4,cs*4+4).
// Full rounds (4 iterations): phase 1 reads the 4 src words (LDS.32) and issues all 4
// xl LDGs (4-deep MLP); phase 2 computes, re-reading full records from smem.
// fill() clamps OOB records to record 0 (valid src), so no select on the gather address.
template <int MODE>
__global__ void __launch_bounds__(256, 2)
gat_aggr_kernel(const float* __restrict__ We, const float* __restrict__ att,
                const float* __restrict__ bias, float invE, int n, int hsel,
                float* __restrict__ out) {
    __shared__ __align__(16) char ringbuf[8 * 3 * 512];  // 8 warps x 3 rounds x 512B
    __shared__ float sWem[HC];   // ee_mean = (mean ea) @ We
    __shared__ float sb[HC];
    __shared__ float swf[HC + 1];
    __shared__ float sst[2 * HC];
    int t = threadIdx.x;
    if (t < HC) {
        sb[t] = bias[t];
        float s = 0.f;
#pragma unroll
        for (int k = 0; k < FE; k++) s += g_eamean[k] * invE * We[k * HC + t];
        sWem[t] = s;
    }
    if (MODE == 0 && t < 2 * HC) sst[t] = 0.f;
    if (MODE == 1 && t < HC + 1) swf[t] = g_weff[t];
    __syncthreads();

    const unsigned FULL = 0xffffffffu;
    int lane = threadIdx.x & 31;
    int warpid = threadIdx.x >> 5;
    int g = lane >> 3, cs = lane & 7;

    float4 wk[FE];
#pragma unroll
    for (int k = 0; k < FE; k++) wk[k] = *(const float4*)(We + k * HC + cs * 4);
    float4 att4 = *(const float4*)(att + cs * 4);

    int i = (blockIdx.x * blockDim.x + threadIdx.x) >> 5;
    if (i < n) {
        int r0 = g_rowptr[i];
        int deg = g_rowptr[i + 1] - r0;
        float4 xr4 = *(const float4*)(g_xr + (size_t)i * HC + cs * 4);
        float4 acc = make_float4(0.f, 0.f, 0.f, 0.f);
        float den = 0.f;

        const char* peb = (const char*)g_pedge + (size_t)r0 * 32;
        char* ringw = ringbuf + warpid * 1536;
        uint32_t ru32 = smem_u32(ringw);

        int nit = (deg + 3) >> 2;       // iterations of 4 edges
        int nrounds = (nit + 3) >> 2;   // rounds of 16 records

        auto fill = [&](int j) {
            int r = j * 16 + (lane >> 1);
            int rc = (r < deg) ? r : 0;
            uint32_t dst = ru32 + (uint32_t)(j % 3) * 512u + (uint32_t)lane * 16u;
            CP_ASYNC16(dst, peb + (size_t)rc * 32 + (lane & 1) * 16);
            CP_COMMIT();
        };
        fill(0);
        fill(1);

        for (int j = 0; j < nrounds; j++) {
            CP_WAIT1();
            __syncwarp();
            fill(j + 2);
            const char* slotb = ringw + (j % 3) * 512 + (g << 5);
            int itb = j * 4;             // first iteration of this round
            int tmax = nit - itb; if (tmax > 4) tmax = 4;

            if (tmax == 4) {
                // phase 1: src words + 4-deep xl gather MLP
                float4 xl[4];
#pragma unroll
                for (int tt = 0; tt < 4; tt++) {
                    int src = __float_as_int(*(const float*)(slotb + (tt << 7) + 28));
                    xl[tt] = *(const float4*)(g_xl + (size_t)src * HC + cs * 4);
                }
                // phase 2: compute (records re-read from resident smem)
#pragma unroll
                for (int tt = 0; tt < 4; tt++) {
                    const char* recp = slotb + (tt << 7);
                    float4 a0 = *(const float4*)recp;
                    float4 a1 = *(const float4*)(recp + 16);
                    bool valid = ((itb + tt) * 4 + g) < deg;

                    float e0 = fmaf(a0.x, wk[0].x, xr4.x);
                    float e1 = fmaf(a0.x, wk[0].y, xr4.y);
                    float e2 = fmaf(a0.x, wk[0].z, xr4.z);
                    float e3 = fmaf(a0.x, wk[0].w, xr4.w);
                    e0 = fmaf(a0.y, wk[1].x, e0); e1 = fmaf(a0.y, wk[1].y, e1);
                    e2 = fmaf(a0.y, wk[1].z, e2); e3 = fmaf(a0.y, wk[1].w, e3);
                    e0 = fmaf(a0.z, wk[2].x, e0); e1 = fmaf(a0.z, wk[2].y, e1);
                    e2 = fmaf(a0.z, wk[2].z, e2); e3 = fmaf(a0.z, wk[2].w, e3);
                    e0 = fmaf(a0.w, wk[3].x, e0); e1 = fmaf(a0.w, wk[3].y, e1);
                    e2 = fmaf(a0.w, wk[3].z, e2); e3 = fmaf(a0.w, wk[3].w, e3);
                    e0 = fmaf(a1.x, wk[4].x, e0); e1 = fmaf(a1.x, wk[4].y, e1);
                    e2 = fmaf(a1.x, wk[4].z, e2); e3 = fmaf(a1.x, wk[4].w, e3);
                    e0 = fmaf(a1.y, wk[5].x, e0); e1 = fmaf(a1.y, wk[5].y, e1);
                    e2 = fmaf(a1.y, wk[5].z, e2); e3 = fmaf(a1.y, wk[5].w, e3);
                    e0 = fmaf(a1.z, wk[6].x, e0); e1 = fmaf(a1.z, wk[6].y, e1);
                    e2 = fmaf(a1.z, wk[6].z, e2); e3 = fmaf(a1.z, wk[6].w, e3);

                    float m0 = lrelu(xl[tt].x + e0, 0.2f);
                    float m1 = lrelu(xl[tt].y + e1, 0.2f);
                    float m2 = lrelu(xl[tt].z + e2, 0.2f);
                    float m3 = lrelu(xl[tt].w + e3, 0.2f);
                    float pl = fmaf(m0, att4.x, fmaf(m1, att4.y, fmaf(m2, att4.z, m3 * att4.w)));
                    float lg = pl + __shfl_xor_sync(FULL, pl, 1);
                    float ex = valid ? __expf(lg) : 0.f;
                    den += ex;
                    acc.x = fmaf(ex, xl[tt].x, acc.x);
                    acc.y = fmaf(ex, xl[tt].y, acc.y);
                    acc.z = fmaf(ex, xl[tt].z, acc.z);
                    acc.w = fmaf(ex, xl[tt].w, acc.w);
                }
            } else {
                for (int tt = 0; tt < tmax; tt++) {
                    const char* recp = slotb + (tt << 7);
                    float4 a0 = *(const float4*)recp;
                    float4 a1 = *(const float4*)(recp + 16);
                    bool valid = ((itb + tt) * 4 + g) < deg;
                    int s = __float_as_int(a1.w);
                    float4 xl4 = *(const float4*)(g_xl + (size_t)s * HC + cs * 4);

                    float e0 = fmaf(a0.x, wk[0].x, xr4.x);
                    float e1 = fmaf(a0.x, wk[0].y, xr4.y);
                    float e2 = fmaf(a0.x, wk[0].z, xr4.z);
                    float e3 = fmaf(a0.x, wk[0].w, xr4.w);
                    e0 = fmaf(a0.y, wk[1].x, e0); e1 = fmaf(a0.y, wk[1].y, e1);
                    e2 = fmaf(a0.y, wk[1].z, e2); e3 = fmaf(a0.y, wk[1].w, e3);
                    e0 = fmaf(a0.z, wk[2].x, e0); e1 = fmaf(a0.z, wk[2].y, e1);
                    e2 = fmaf(a0.z, wk[2].z, e2); e3 = fmaf(a0.z, wk[2].w, e3);
                    e0 = fmaf(a0.w, wk[3].x, e0); e1 = fmaf(a0.w, wk[3].y, e1);
                    e2 = fmaf(a0.w, wk[3].z, e2); e3 = fmaf(a0.w, wk[3].w, e3);
                    e0 = fmaf(a1.x, wk[4].x, e0); e1 = fmaf(a1.x, wk[4].y, e1);
                    e2 = fmaf(a1.x, wk[4].z, e2); e3 = fmaf(a1.x, wk[4].w, e3);
                    e0 = fmaf(a1.y, wk[5].x, e0); e1 = fmaf(a1.y, wk[5].y, e1);
                    e2 = fmaf(a1.y, wk[5].z, e2); e3 = fmaf(a1.y, wk[5].w, e3);
                    e0 = fmaf(a1.z, wk[6].x, e0); e1 = fmaf(a1.z, wk[6].y, e1);
                    e2 = fmaf(a1.z, wk[6].z, e2); e3 = fmaf(a1.z, wk[6].w, e3);

                    float m0 = lrelu(xl4.x + e0, 0.2f);
                    float m1 = lrelu(xl4.y + e1, 0.2f);
                    float m2 = lrelu(xl4.z + e2, 0.2f);
                    float m3 = lrelu(xl4.w + e3, 0.2f);
                    float pl = fmaf(m0, att4.x, fmaf(m1, att4.y, fmaf(m2, att4.z, m3 * att4.w)));
                    float lg = pl + __shfl_xor_sync(FULL, pl, 1);
                    float ex = valid ? __expf(lg) : 0.f;
                    den += ex;
                    acc.x = fmaf(ex, xl4.x, acc.x);
                    acc.y = fmaf(ex, xl4.y, acc.y);
                    acc.z = fmaf(ex, xl4.z, acc.z);
                    acc.w = fmaf(ex, xl4.w, acc.w);
                }
            }
        }

        // self-loop contribution (ea = mean): all lanes compute; group 0 accumulates
        {
            float4 xli = *(const float4*)(g_xl + (size_t)i * HC + cs * 4);
            float m0 = lrelu(xli.x + xr4.x + sWem[cs * 4 + 0], 0.2f);
            float m1 = lrelu(xli.y + xr4.y + sWem[cs * 4 + 1], 0.2f);
            float m2 = lrelu(xli.z + xr4.z + sWem[cs * 4 + 2], 0.2f);
            float m3 = lrelu(xli.w + xr4.w + sWem[cs * 4 + 3], 0.2f);
            float pl = fmaf(m0, att4.x, fmaf(m1, att4.y, fmaf(m2, att4.z, m3 * att4.w)));
            float lg = pl + __shfl_xor_sync(FULL, pl, 1);
            float ex = __expf(lg);
            if (g == 0) {
                den += ex;
                acc.x = fmaf(ex, xli.x, acc.x);
                acc.y = fmaf(ex, xli.y, acc.y);
                acc.z = fmaf(ex, xli.z, acc.z);
                acc.w = fmaf(ex, xli.w, acc.w);
            }
        }

#pragma unroll
        for (int off = 8; off < 32; off <<= 1) {
            acc.x += __shfl_xor_sync(FULL, acc.x, off);
            acc.y += __shfl_xor_sync(FULL, acc.y, off);
            acc.z += __shfl_xor_sync(FULL, acc.z, off);
            acc.w += __shfl_xor_sync(FULL, acc.w, off);
            den   += __shfl_xor_sync(FULL, den,   off);
        }
        if (g == 0) {
            float inv = 1.f / (den + 1e-16f);
            float h0 = acc.x * inv + sb[cs * 4];
            float h1 = acc.y * inv + sb[cs * 4 + 1];
            float h2 = acc.z * inv + sb[cs * 4 + 2];
            float h3 = acc.w * inv + sb[cs * 4 + 3];
            if (MODE == 0) {
                float* hp = (hsel ? g_h2 : g_h1) + (size_t)i * HC + cs * 4;
                *(float4*)hp = make_float4(h0, h1, h2, h3);
                atomicAdd(&sst[cs * 4 + 0], h0);
                atomicAdd(&sst[cs * 4 + 1], h1);
                atomicAdd(&sst[cs * 4 + 2], h2);
                atomicAdd(&sst[cs * 4 + 3], h3);
                atomicAdd(&sst[HC + cs * 4 + 0], h0 * h0);
                atomicAdd(&sst[HC + cs * 4 + 1], h1 * h1);
                atomicAdd(&sst[HC + cs * 4 + 2], h2 * h2);
                atomicAdd(&sst[HC + cs * 4 + 3], h3 * h3);
            } else {
                float s = lrelu(h0, 0.01f) * swf[cs * 4]
                        + lrelu(h1, 0.01f) * swf[cs * 4 + 1]
                        + lrelu(h2, 0.01f) * swf[cs * 4 + 2]
                        + lrelu(h3, 0.01f) * swf[cs * 4 + 3];
                s += __shfl_xor_sync(0x000000ffu, s, 1);
                s += __shfl_xor_sync(0x000000ffu, s, 2);
                s += __shfl_xor_sync(0x000000ffu, s, 4);
                if (cs == 0) out[i] = s + swf[HC];
            }
        }
    }
    if (MODE == 0) {
        __syncthreads();
        if (t < 2 * HC) atomicAdd(&g_stats[t], sst[t]);
    }
}

__global__ void bn_finalize_kernel(const float* __restrict__ gamma,
                                   const float* __restrict__ beta, float invn) {
    int c = threadIdx.x;
    if (c >= HC) return;
    float mu = g_stats[c] * invn;
    float var = g_stats[HC + c] * invn - mu * mu;
    float A = rsqrtf(var + 1e-5f) * gamma[c];
    g_ab[c] = A;
    g_ab[HC + c] = beta[c] - mu * A;
}

// ---------------- launch ----------------
extern "C" void kernel_launch(void* const* d_in, const int* in_sizes, int n_in,
                              void* d_out, int out_size) {
    const float* x    = (const float*)d_in[0];
    const int*   eidx = (const int*)d_in[1];
    const float* ea   = (const float*)d_in[2];
    const float* Wl1 = (const float*)d_in[3];  const float* bl1 = (const float*)d_in[4];
    const float* Wr1 = (const float*)d_in[5];  const float* br1 = (const float*)d_in[6];
    const float* We1 = (const float*)d_in[7];  const float* att1 = (const float*)d_in[8];
    const float* b1  = (const float*)d_in[9];
    const float* Wl2 = (const float*)d_in[10]; const float* bl2 = (const float*)d_in[11];
    const float* Wr2 = (const float*)d_in[12]; const float* br2 = (const float*)d_in[13];
    const float* We2 = (const float*)d_in[14]; const float* att2 = (const float*)d_in[15];
    const float* b2  = (const float*)d_in[16];
    const float* gamma = (const float*)d_in[17]; const float* beta = (const float*)d_in[18];
    const float* Wreg = (const float*)d_in[19];  const float* breg = (const float*)d_in[20];
    const float* Wend = (const float*)d_in[21];  const float* bend = (const float*)d_in[22];
    float* out = (float*)d_out;

    int n = in_sizes[0] / FN;
    int E = in_sizes[1] / 2;
    float invE = 1.f / (float)E;
    int nbN = (n + 255) / 256;
    int nbE = (E + 255) / 256;
    int nbW = (n * 32 + 255) / 256;

    t1_hist_kernel<<<nbN + nbE, 256>>>(x, Wl1, bl1, Wr1, br1, n, eidx, E, nbN); // 0
    scan_kernel<<<1, 1024>>>(n);                                                // 1
    scatter_kernel<<<nbE, 256>>>(eidx, ea, E);                                  // 2
    gat_aggr_kernel<0><<<nbW, 256>>>(We1, att1, b1, invE, n, 0, nullptr);       // 3 <- profiled
    bn_finalize_kernel<<<1, 32>>>(gamma, beta, 1.f / (float)n);                 // 4

    transform_kernel<<<nbN, 256>>>(0, Wl2, bl2, Wr2, br2, n);                   // 5
    gat_aggr_kernel<0><<<nbW, 256>>>(We2, att2, b2, invE, n, 1, nullptr);       // 6
    bn_finalize_kernel<<<1, 32>>>(gamma, beta, 1.f / (float)n);                 // 7

    transform_kernel<<<nbN, 256>>>(1, Wl2, bl2, Wr2, br2, n);                   // 8
    weff_kernel<<<1, 1024>>>(Wreg, breg, Wend, bend);                           // 9
    gat_aggr_kernel<1><<<nbW, 256>>>(We2, att2, b2, invE, n, 0, out);           // 10
}

// round 13
// speedup vs baseline: 1.2206x; 1.1326x over previous
#include <cuda_runtime.h>
#include <math.h>
#include <stdint.h>

#define NN   100000
#define FN   2
#define FE   7
#define NH   4
#define HC   32
#define EMAX 3200000
#define REGF 500

#define CP_ASYNC16(dst, src) \
    asm volatile("cp.async.cg.shared.global [%0], [%1], 16;" :: "r"(dst), "l"(src) : "memory")
#define CP_COMMIT() asm volatile("cp.async.commit_group;" ::: "memory")
#define CP_WAIT1()  asm volatile("cp.async.wait_group 1;" ::: "memory")

#define PACK_F32X2(out, lo, hi) \
    asm("mov.b64 %0, {%1, %2};" : "=l"(out) : "f"(lo), "f"(hi))
#define UNPACK_F32X2(lo, hi, in) \
    asm("mov.b64 {%0, %1}, %2;" : "=f"(lo), "=f"(hi) : "l"(in))
#define FMA_F32X2(d, a, b, c) \
    asm("fma.rn.f32x2 %0, %1, %2, %3;" : "=l"(d) : "l"(a), "l"(b), "l"(c))

__device__ __forceinline__ uint32_t smem_u32(const void* p) {
    uint32_t a;
    asm("{ .reg .u64 t; cvta.to.shared.u64 t, %1; cvt.u32.u64 %0, t; }" : "=r"(a) : "l"(p));
    return a;
}

// ---------------- scratch (static device globals; no runtime alloc) ----------------
__device__ float g_xl[(size_t)NN * HC];
__device__ float g_xr[(size_t)NN * HC];
__device__ float g_h1[(size_t)NN * HC];
__device__ float g_h2[(size_t)NN * HC];
__device__ __align__(16) int g_cnt[NN];   // zero at load; scan re-zeros after reading
__device__ int   g_rowptr[NN + 1];
__device__ int   g_cur[NN];
__device__ __align__(16) float g_pedge[(size_t)EMAX * 8 + 8];  // 32B rec: [0..6]=ea, [7]=src (+pad)
__device__ float g_eamean[FE];
__device__ float g_stats[2 * HC];
__device__ float g_ab[2 * HC];
__device__ float g_weff[HC + 1];

__device__ __forceinline__ float lrelu(float x, float s) { return fmaxf(x, s * x); }

// ---------------- fused: transform layer-1 (node blocks) + degree hist (edge blocks) ----
__global__ void t1_hist_kernel(const float* __restrict__ x,
                               const float* __restrict__ Wl, const float* __restrict__ bl,
                               const float* __restrict__ Wr, const float* __restrict__ br,
                               int n, const int* __restrict__ eidx, int E, int nbN) {
    if ((int)blockIdx.x >= nbN) {  // histogram part
        int e = (blockIdx.x - nbN) * blockDim.x + threadIdx.x;
        if (e < E) atomicAdd(&g_cnt[eidx[E + e]], 1);
        return;
    }
    __shared__ float sWl[FN * HC], sWr[FN * HC], sb[2 * HC];
    for (int t = threadIdx.x; t < FN * HC; t += blockDim.x) { sWl[t] = Wl[t]; sWr[t] = Wr[t]; }
    for (int t = threadIdx.x; t < HC; t += blockDim.x) { sb[t] = bl[t]; sb[HC + t] = br[t]; }
    if (blockIdx.x == 0 && threadIdx.x < 2 * HC) g_stats[threadIdx.x] = 0.f;
    __syncthreads();
    int i = blockIdx.x * blockDim.x + threadIdx.x;
    if (i >= n) return;
    float in0 = x[(size_t)i * FN], in1 = x[(size_t)i * FN + 1];
    float vl[HC], vr[HC];
#pragma unroll
    for (int c = 0; c < HC; c++) {
        vl[c] = sb[c] + in0 * sWl[c] + in1 * sWl[HC + c];
        vr[c] = sb[HC + c] + in0 * sWr[c] + in1 * sWr[HC + c];
    }
    float4* pl = (float4*)(g_xl + (size_t)i * HC);
    float4* pr = (float4*)(g_xr + (size_t)i * HC);
#pragma unroll
    for (int q = 0; q < 8; q++) {
        pl[q] = make_float4(vl[q * 4], vl[q * 4 + 1], vl[q * 4 + 2], vl[q * 4 + 3]);
        pr[q] = make_float4(vr[q * 4], vr[q * 4 + 1], vr[q * 4 + 2], vr[q * 4 + 3]);
    }
}

// single-block scan (int4 read pass); zeros g_eamean; re-zeros g_cnt (replay-safe);
// also computes weff (collapsed Wreg@Wend head) with its 32 warps.
__global__ void scan_kernel(int n, const float* __restrict__ Wreg,
                            const float* __restrict__ breg,
                            const float* __restrict__ Wend,
                            const float* __restrict__ bend) {
    __shared__ int a[1024];
    int t = threadIdx.x;
    if (t < FE) g_eamean[t] = 0.f;

    // weff: warp w computes g_weff[w]; warp 0 lane also does bias term
    {
        int w = t >> 5, lane = t & 31;
        float s = 0.f;
        for (int r = lane; r < REGF; r += 32) s += Wreg[w * REGF + r] * Wend[r];
#pragma unroll
        for (int o = 16; o > 0; o >>= 1) s += __shfl_down_sync(0xffffffffu, s, o);
        if (lane == 0) g_weff[w] = s;
        if (w == 0) {
            float b = 0.f;
            for (int r = lane; r < REGF; r += 32) b += breg[r] * Wend[r];
#pragma unroll
            for (int o = 16; o > 0; o >>= 1) b += __shfl_down_sync(0xffffffffu, b, o);
            if (lane == 0) g_weff[HC] = b + bend[0];
        }
    }

    const int chunk = 100;   // 400B per thread: 16B-aligned, 25 int4s
    int lo = t * chunk;
    int hi = lo + chunk; if (hi > n) hi = n; if (lo > n) lo = n;
    int s = 0;
    if (lo < hi) {
        const int4* p4 = (const int4*)(g_cnt + lo);
        int nfull = (hi - lo) >> 2;
        for (int q = 0; q < nfull; q++) {
            int4 v = p4[q];
            s += v.x + v.y + v.z + v.w;
        }
        for (int i = lo + nfull * 4; i < hi; i++) s += g_cnt[i];
    }
    a[t] = s;
    __syncthreads();
    for (int off = 1; off < 1024; off <<= 1) {
        int u = (t >= off) ? a[t - off] : 0;
        __syncthreads();
        a[t] += u;
        __syncthreads();
    }
    int run = a[t] - s;
    for (int i = lo; i < hi; i++) {
        int c = g_cnt[i];
        g_cnt[i] = 0;
        g_rowptr[i] = run;
        g_cur[i] = run;
        run += c;
    }
    if (t == 1023) g_rowptr[n] = a[1023];
}

// scatter edges into CSR order (32B record); accumulates ea sums
__global__ void scatter_kernel(const int* __restrict__ eidx, const float* __restrict__ ea, int E) {
    __shared__ float sh[FE];
    if (threadIdx.x < FE) sh[threadIdx.x] = 0.f;
    __syncthreads();
    int e = blockIdx.x * blockDim.x + threadIdx.x;
    float v[FE];
    if (e < E) {
        int s = eidx[e];
        int d = eidx[E + e];
#pragma unroll
        for (int k = 0; k < FE; k++) v[k] = ea[(size_t)e * FE + k];
        int pos = atomicAdd(&g_cur[d], 1);
        float4* rec = (float4*)(g_pedge + (size_t)pos * 8);
        rec[0] = make_float4(v[0], v[1], v[2], v[3]);
        rec[1] = make_float4(v[4], v[5], v[6], __int_as_float(s));
    } else {
#pragma unroll
        for (int k = 0; k < FE; k++) v[k] = 0.f;
    }
#pragma unroll
    for (int k = 0; k < FE; k++) {
        float x = v[k];
#pragma unroll
        for (int o = 16; o > 0; o >>= 1) x += __shfl_down_sync(0xffffffffu, x, o);
        if ((threadIdx.x & 31) == 0) atomicAdd(&sh[k], x);
    }
    __syncthreads();
    if (threadIdx.x < FE) atomicAdd(&g_eamean[threadIdx.x], sh[threadIdx.x]);
}

// ---- node transform for layers 2/3 (F=HC, BN+act fused) ----
__global__ void transform_kernel(int insel,
                                 const float* __restrict__ Wl, const float* __restrict__ bl,
                                 const float* __restrict__ Wr, const float* __restrict__ br,
                                 int n) {
    __shared__ float sWl[HC * HC], sWr[HC * HC], sb[2 * HC];
    for (int t = threadIdx.x; t < HC * HC; t += blockDim.x) { sWl[t] = Wl[t]; sWr[t] = Wr[t]; }
    for (int t = threadIdx.x; t < HC; t += blockDim.x) { sb[t] = bl[t]; sb[HC + t] = br[t]; }
    if (blockIdx.x == 0 && threadIdx.x < 2 * HC) g_stats[threadIdx.x] = 0.f;
    __syncthreads();
    int i = blockIdx.x * blockDim.x + threadIdx.x;
    if (i >= n) return;
    const float* hin = insel ? g_h2 : g_h1;

    float in[HC];
#pragma unroll
    for (int k = 0; k < HC; k++) {
        float v = hin[(size_t)i * HC + k];
        v = v * g_ab[k] + g_ab[HC + k];
        in[k] = lrelu(v, 0.01f);
    }
    float vl[HC], vr[HC];
#pragma unroll
    for (int c = 0; c < HC; c++) { vl[c] = sb[c]; vr[c] = sb[HC + c]; }
#pragma unroll
    for (int k = 0; k < HC; k++) {
        float a = in[k];
#pragma unroll
        for (int c = 0; c < HC; c++) { vl[c] += a * sWl[k * HC + c]; vr[c] += a * sWr[k * HC + c]; }
    }
    float4* pl = (float4*)(g_xl + (size_t)i * HC);
    float4* pr = (float4*)(g_xr + (size_t)i * HC);
#pragma unroll
    for (int q = 0; q < 8; q++) {
        pl[q] = make_float4(vl[q * 4], vl[q * 4 + 1], vl[q * 4 + 2], vl[q * 4 + 3]);
        pr[q] = make_float4(vr[q * 4], vr[q * 4 + 1], vr[q * 4 + 2], vr[q * 4 + 3]);
    }
}

// ---------------- warp-per-node GATv2 aggregation, cp.async ring (R10) + f32x2 ---------
// group g = lane>>3 owns one edge per iteration; cs = lane&7 owns channels [cs*4,cs*4+4).
// Records stream DRAM->smem via cp.async (3-slot ring, 2 in flight); LDS consumption.
// e-transform uses packed fma.rn.f32x2 (identical rounding, half the FMA-pipe ops).
template <int MODE>
__global__ void __launch_bounds__(256, 3)
gat_aggr_kernel(const float* __restrict__ We, const float* __restrict__ att,
                const float* __restrict__ bias, float invE, int n, int hsel,
                float* __restrict__ out) {
    __shared__ __align__(16) char ringbuf[8 * 3 * 512];  // 8 warps x 3 rounds x 512B
    __shared__ float sWem[HC];   // ee_mean = (mean ea) @ We
    __shared__ float sb[HC];
    __shared__ float swf[HC + 1];
    __shared__ float sst[2 * HC];
    int t = threadIdx.x;
    if (t < HC) {
        sb[t] = bias[t];
        float s = 0.f;
#pragma unroll
        for (int k = 0; k < FE; k++) s += g_eamean[k] * invE * We[k * HC + t];
        sWem[t] = s;
    }
    if (MODE == 0 && t < 2 * HC) sst[t] = 0.f;
    if (MODE == 1 && t < HC + 1) swf[t] = g_weff[t];
    __syncthreads();

    const unsigned FULL = 0xffffffffu;
    int lane = threadIdx.x & 31;
    int warpid = threadIdx.x >> 5;
    int g = lane >> 3, cs = lane & 7;

    // per-lane We slice packed as f32x2 pairs; att slice
    uint64_t wk01[FE], wk23[FE];
#pragma unroll
    for (int k = 0; k < FE; k++) {
        float4 w = *(const float4*)(We + k * HC + cs * 4);
        PACK_F32X2(wk01[k], w.x, w.y);
        PACK_F32X2(wk23[k], w.z, w.w);
    }
    float4 att4 = *(const float4*)(att + cs * 4);

    int i = (blockIdx.x * blockDim.x + threadIdx.x) >> 5;
    if (i < n) {
        int r0 = g_rowptr[i];
        int deg = g_rowptr[i + 1] - r0;
        float4 xr4 = *(const float4*)(g_xr + (size_t)i * HC + cs * 4);
        uint64_t xr01, xr23;
        PACK_F32X2(xr01, xr4.x, xr4.y);
        PACK_F32X2(xr23, xr4.z, xr4.w);
        float4 acc = make_float4(0.f, 0.f, 0.f, 0.f);
        float den = 0.f;

        const char* peb = (const char*)g_pedge + (size_t)r0 * 32;
        char* ringw = ringbuf + warpid * 1536;
        uint32_t ru32 = smem_u32(ringw);

        int nit = (deg + 3) >> 2;       // iterations of 4 edges
        int nrounds = (nit + 3) >> 2;   // rounds of 16 records

        auto fill = [&](int j) {
            int r = j * 16 + (lane >> 1);
            int rc = (r < deg) ? r : 0;
            uint32_t dst = ru32 + (uint32_t)(j % 3) * 512u + (uint32_t)lane * 16u;
            CP_ASYNC16(dst, peb + (size_t)rc * 32 + (lane & 1) * 16);
            CP_COMMIT();
        };
        fill(0);
        fill(1);

        int it = 0;
        for (int j = 0; j < nrounds; j++) {
            CP_WAIT1();
            __syncwarp();
            fill(j + 2);
            const char* slotb = ringw + (j % 3) * 512;
            int tmax = nit - j * 4; if (tmax > 4) tmax = 4;
            for (int tt = 0; tt < tmax; tt++, it++) {
                int r = it * 4 + g;
                bool valid = r < deg;
                const char* recp = slotb + (tt * 4 + g) * 32;
                float4 a0 = *(const float4*)recp;
                float4 a1 = *(const float4*)(recp + 16);

                int s = valid ? __float_as_int(a1.w) : i;
                float4 xl4 = *(const float4*)(g_xl + (size_t)s * HC + cs * 4);

                // e-transform, packed f32x2, accumulator pre-seeded with xr
                float av[FE] = {a0.x, a0.y, a0.z, a0.w, a1.x, a1.y, a1.z};
                uint64_t e01 = xr01, e23 = xr23;
#pragma unroll
                for (int k = 0; k < FE; k++) {
                    uint64_t aa;
                    PACK_F32X2(aa, av[k], av[k]);
                    FMA_F32X2(e01, aa, wk01[k], e01);
                    FMA_F32X2(e23, aa, wk23[k], e23);
                }
                float e0, e1, e2, e3;
                UNPACK_F32X2(e0, e1, e01);
                UNPACK_F32X2(e2, e3, e23);

                float m0 = lrelu(xl4.x + e0, 0.2f);
                float m1 = lrelu(xl4.y + e1, 0.2f);
                float m2 = lrelu(xl4.z + e2, 0.2f);
                float m3 = lrelu(xl4.w + e3, 0.2f);
                float pl = fmaf(m0, att4.x, fmaf(m1, att4.y, fmaf(m2, att4.z, m3 * att4.w)));
                float lg = pl + __shfl_xor_sync(FULL, pl, 1);
                float ex = valid ? __expf(lg) : 0.f;
                den += ex;
                acc.x = fmaf(ex, xl4.x, acc.x);
                acc.y = fmaf(ex, xl4.y, acc.y);
                acc.z = fmaf(ex, xl4.z, acc.z);
                acc.w = fmaf(ex, xl4.w, acc.w);
            }
        }

        // self-loop contribution (ea = mean): all lanes compute; group 0 accumulates
        {
            float4 xli = *(const float4*)(g_xl + (size_t)i * HC + cs * 4);
            float m0 = lrelu(xli.x + xr4.x + sWem[cs * 4 + 0], 0.2f);
            float m1 = lrelu(xli.y + xr4.y + sWem[cs * 4 + 1], 0.2f);
            float m2 = lrelu(xli.z + xr4.z + sWem[cs * 4 + 2], 0.2f);
            float m3 = lrelu(xli.w + xr4.w + sWem[cs * 4 + 3], 0.2f);
            float pl = fmaf(m0, att4.x, fmaf(m1, att4.y, fmaf(m2, att4.z, m3 * att4.w)));
            float lg = pl + __shfl_xor_sync(FULL, pl, 1);
            float ex = __expf(lg);
            if (g == 0) {
                den += ex;
                acc.x = fmaf(ex, xli.x, acc.x);
                acc.y = fmaf(ex, xli.y, acc.y);
                acc.z = fmaf(ex, xli.z, acc.z);
                acc.w = fmaf(ex, xli.w, acc.w);
            }
        }

#pragma unroll
        for (int off = 8; off < 32; off <<= 1) {
            acc.x += __shfl_xor_sync(FULL, acc.x, off);
            acc.y += __shfl_xor_sync(FULL, acc.y, off);
            acc.z += __shfl_xor_sync(FULL, acc.z, off);
            acc.w += __shfl_xor_sync(FULL, acc.w, off);
            den   += __shfl_xor_sync(FULL, den,   off);
        }
        if (g == 0) {
            float inv = 1.f / (den + 1e-16f);
            float h0 = acc.x * inv + sb[cs * 4];
            float h1 = acc.y * inv + sb[cs * 4 + 1];
            float h2 = acc.z * inv + sb[cs * 4 + 2];
            float h3 = acc.w * inv + sb[cs * 4 + 3];
            if (MODE == 0) {
                float* hp = (hsel ? g_h2 : g_h1) + (size_t)i * HC + cs * 4;
                *(float4*)hp = make_float4(h0, h1, h2, h3);
                atomicAdd(&sst[cs * 4 + 0], h0);
                atomicAdd(&sst[cs * 4 + 1], h1);
                atomicAdd(&sst[cs * 4 + 2], h2);
                atomicAdd(&sst[cs * 4 + 3], h3);
                atomicAdd(&sst[HC + cs * 4 + 0], h0 * h0);
                atomicAdd(&sst[HC + cs * 4 + 1], h1 * h1);
                atomicAdd(&sst[HC + cs * 4 + 2], h2 * h2);
                atomicAdd(&sst[HC + cs * 4 + 3], h3 * h3);
            } else {
                float s = lrelu(h0, 0.01f) * swf[cs * 4]
                        + lrelu(h1, 0.01f) * swf[cs * 4 + 1]
                        + lrelu(h2, 0.01f) * swf[cs * 4 + 2]
                        + lrelu(h3, 0.01f) * swf[cs * 4 + 3];
                s += __shfl_xor_sync(0x000000ffu, s, 1);
                s += __shfl_xor_sync(0x000000ffu, s, 2);
                s += __shfl_xor_sync(0x000000ffu, s, 4);
                if (cs == 0) out[i] = s + swf[HC];
            }
        }
    }
    if (MODE == 0) {
        __syncthreads();
        if (t < 2 * HC) atomicAdd(&g_stats[t], sst[t]);
    }
}

__global__ void bn_finalize_kernel(const float* __restrict__ gamma,
                                   const float* __restrict__ beta, float invn) {
    int c = threadIdx.x;
    if (c >= HC) return;
    float mu = g_stats[c] * invn;
    float var = g_stats[HC + c] * invn - mu * mu;
    float A = rsqrtf(var + 1e-5f) * gamma[c];
    g_ab[c] = A;
    g_ab[HC + c] = beta[c] - mu * A;
}

// ---------------- launch ----------------
extern "C" void kernel_launch(void* const* d_in, const int* in_sizes, int n_in,
                              void* d_out, int out_size) {
    const float* x    = (const float*)d_in[0];
    const int*   eidx = (const int*)d_in[1];
    const float* ea   = (const float*)d_in[2];
    const float* Wl1 = (const float*)d_in[3];  const float* bl1 = (const float*)d_in[4];
    const float* Wr1 = (const float*)d_in[5];  const float* br1 = (const float*)d_in[6];
    const float* We1 = (const float*)d_in[7];  const float* att1 = (const float*)d_in[8];
    const float* b1  = (const float*)d_in[9];
    const float* Wl2 = (const float*)d_in[10]; const float* bl2 = (const float*)d_in[11];
    const float* Wr2 = (const float*)d_in[12]; const float* br2 = (const float*)d_in[13];
    const float* We2 = (const float*)d_in[14]; const float* att2 = (const float*)d_in[15];
    const float* b2  = (const float*)d_in[16];
    const float* gamma = (const float*)d_in[17]; const float* beta = (const float*)d_in[18];
    const float* Wreg = (const float*)d_in[19];  const float* breg = (const float*)d_in[20];
    const float* Wend = (const float*)d_in[21];  const float* bend = (const float*)d_in[22];
    float* out = (float*)d_out;

    int n = in_sizes[0] / FN;
    int E = in_sizes[1] / 2;
    float invE = 1.f / (float)E;
    int nbN = (n + 255) / 256;
    int nbE = (E + 255) / 256;
    int nbW = (n * 32 + 255) / 256;

    t1_hist_kernel<<<nbN + nbE, 256>>>(x, Wl1, bl1, Wr1, br1, n, eidx, E, nbN); // 0
    scan_kernel<<<1, 1024>>>(n, Wreg, breg, Wend, bend);                        // 1
    scatter_kernel<<<nbE, 256>>>(eidx, ea, E);                                  // 2
    gat_aggr_kernel<0><<<nbW, 256>>>(We1, att1, b1, invE, n, 0, nullptr);       // 3 <- profiled
    bn_finalize_kernel<<<1, 32>>>(gamma, beta, 1.f / (float)n);                 // 4

    transform_kernel<<<nbN, 256>>>(0, Wl2, bl2, Wr2, br2, n);                   // 5
    gat_aggr_kernel<0><<<nbW, 256>>>(We2, att2, b2, invE, n, 1, nullptr);       // 6
    bn_finalize_kernel<<<1, 32>>>(gamma, beta, 1.f / (float)n);                 // 7

    transform_kernel<<<nbN, 256>>>(1, Wl2, bl2, Wr2, br2, n);                   // 8
    gat_aggr_kernel<1><<<nbW, 256>>>(We2, att2, b2, invE, n, 0, out);           // 9
}

// round 14
// speedup vs baseline: 1.2505x; 1.0245x over previous
#include <cuda_runtime.h>
#include <math.h>
#include <stdint.h>

#define NN   100000
#define FN   2
#define FE   7
#define NH   4
#define HC   32
#define EMAX 3200000
#define REGF 500

#define CP_ASYNC16(dst, src) \
    asm volatile("cp.async.cg.shared.global [%0], [%1], 16;" :: "r"(dst), "l"(src) : "memory")
#define CP_COMMIT() asm volatile("cp.async.commit_group;" ::: "memory")
#define CP_WAIT1()  asm volatile("cp.async.wait_group 1;" ::: "memory")

#define PACK_F32X2(out, lo, hi) \
    asm("mov.b64 %0, {%1, %2};" : "=l"(out) : "f"(lo), "f"(hi))
#define UNPACK_F32X2(lo, hi, in) \
    asm("mov.b64 {%0, %1}, %2;" : "=f"(lo), "=f"(hi) : "l"(in))
#define FMA_F32X2(d, a, b, c) \
    asm("fma.rn.f32x2 %0, %1, %2, %3;" : "=l"(d) : "l"(a), "l"(b), "l"(c))

__device__ __forceinline__ uint32_t smem_u32(const void* p) {
    uint32_t a;
    asm("{ .reg .u64 t; cvta.to.shared.u64 t, %1; cvt.u32.u64 %0, t; }" : "=r"(a) : "l"(p));
    return a;
}

// ---------------- scratch (static device globals; no runtime alloc) ----------------
__device__ float g_xl[(size_t)NN * HC];
__device__ float g_xr[(size_t)NN * HC];
__device__ float g_h1[(size_t)NN * HC];
__device__ float g_h2[(size_t)NN * HC];
__device__ __align__(16) int g_cnt[NN];   // zero at load; scan re-zeros after reading
__device__ int   g_rowptr[NN + 1];
__device__ int   g_cur[NN];
__device__ __align__(16) float g_pedge[(size_t)EMAX * 8 + 8];  // 32B rec: [0..6]=ea, [7]=src (+zero pad)
__device__ float g_eamean[FE];
__device__ float g_stats[2 * HC];
__device__ float g_ab[2 * HC];
__device__ float g_weff[HC + 1];

__device__ __forceinline__ float lrelu(float x, float s) { return fmaxf(x, s * x); }

// ---------------- fused: transform layer-1 (node blocks) + degree hist (edge blocks) ----
__global__ void t1_hist_kernel(const float* __restrict__ x,
                               const float* __restrict__ Wl, const float* __restrict__ bl,
                               const float* __restrict__ Wr, const float* __restrict__ br,
                               int n, const int* __restrict__ eidx, int E, int nbN) {
    if ((int)blockIdx.x >= nbN) {  // histogram part
        int e = (blockIdx.x - nbN) * blockDim.x + threadIdx.x;
        if (e < E) atomicAdd(&g_cnt[eidx[E + e]], 1);
        return;
    }
    __shared__ float sWl[FN * HC], sWr[FN * HC], sb[2 * HC];
    for (int t = threadIdx.x; t < FN * HC; t += blockDim.x) { sWl[t] = Wl[t]; sWr[t] = Wr[t]; }
    for (int t = threadIdx.x; t < HC; t += blockDim.x) { sb[t] = bl[t]; sb[HC + t] = br[t]; }
    if (blockIdx.x == 0 && threadIdx.x < 2 * HC) g_stats[threadIdx.x] = 0.f;
    __syncthreads();
    int i = blockIdx.x * blockDim.x + threadIdx.x;
    if (i >= n) return;
    float in0 = x[(size_t)i * FN], in1 = x[(size_t)i * FN + 1];
    float vl[HC], vr[HC];
#pragma unroll
    for (int c = 0; c < HC; c++) {
        vl[c] = sb[c] + in0 * sWl[c] + in1 * sWl[HC + c];
        vr[c] = sb[HC + c] + in0 * sWr[c] + in1 * sWr[HC + c];
    }
    float4* pl = (float4*)(g_xl + (size_t)i * HC);
    float4* pr = (float4*)(g_xr + (size_t)i * HC);
#pragma unroll
    for (int q = 0; q < 8; q++) {
        pl[q] = make_float4(vl[q * 4], vl[q * 4 + 1], vl[q * 4 + 2], vl[q * 4 + 3]);
        pr[q] = make_float4(vr[q * 4], vr[q * 4 + 1], vr[q * 4 + 2], vr[q * 4 + 3]);
    }
}

// single-block scan (int4 read pass); zeros g_eamean; re-zeros g_cnt (replay-safe);
// also computes weff (collapsed Wreg@Wend head) with its 32 warps.
__global__ void scan_kernel(int n, const float* __restrict__ Wreg,
                            const float* __restrict__ breg,
                            const float* __restrict__ Wend,
                            const float* __restrict__ bend) {
    __shared__ int a[1024];
    int t = threadIdx.x;
    if (t < FE) g_eamean[t] = 0.f;

    {
        int w = t >> 5, lane = t & 31;
        float s = 0.f;
        for (int r = lane; r < REGF; r += 32) s += Wreg[w * REGF + r] * Wend[r];
#pragma unroll
        for (int o = 16; o > 0; o >>= 1) s += __shfl_down_sync(0xffffffffu, s, o);
        if (lane == 0) g_weff[w] = s;
        if (w == 0) {
            float b = 0.f;
            for (int r = lane; r < REGF; r += 32) b += breg[r] * Wend[r];
#pragma unroll
            for (int o = 16; o > 0; o >>= 1) b += __shfl_down_sync(0xffffffffu, b, o);
            if (lane == 0) g_weff[HC] = b + bend[0];
        }
    }

    const int chunk = 100;
    int lo = t * chunk;
    int hi = lo + chunk; if (hi > n) hi = n; if (lo > n) lo = n;
    int s = 0;
    if (lo < hi) {
        const int4* p4 = (const int4*)(g_cnt + lo);
        int nfull = (hi - lo) >> 2;
        for (int q = 0; q < nfull; q++) {
            int4 v = p4[q];
            s += v.x + v.y + v.z + v.w;
        }
        for (int i = lo + nfull * 4; i < hi; i++) s += g_cnt[i];
    }
    a[t] = s;
    __syncthreads();
    for (int off = 1; off < 1024; off <<= 1) {
        int u = (t >= off) ? a[t - off] : 0;
        __syncthreads();
        a[t] += u;
        __syncthreads();
    }
    int run = a[t] - s;
    for (int i = lo; i < hi; i++) {
        int c = g_cnt[i];
        g_cnt[i] = 0;
        g_rowptr[i] = run;
        g_cur[i] = run;
        run += c;
    }
    if (t == 1023) g_rowptr[n] = a[1023];
}

// scatter edges into CSR order (32B record); accumulates ea sums
__global__ void scatter_kernel(const int* __restrict__ eidx, const float* __restrict__ ea, int E) {
    __shared__ float sh[FE];
    if (threadIdx.x < FE) sh[threadIdx.x] = 0.f;
    __syncthreads();
    int e = blockIdx.x * blockDim.x + threadIdx.x;
    float v[FE];
    if (e < E) {
        int s = eidx[e];
        int d = eidx[E + e];
#pragma unroll
        for (int k = 0; k < FE; k++) v[k] = ea[(size_t)e * FE + k];
        int pos = atomicAdd(&g_cur[d], 1);
        float4* rec = (float4*)(g_pedge + (size_t)pos * 8);
        rec[0] = make_float4(v[0], v[1], v[2], v[3]);
        rec[1] = make_float4(v[4], v[5], v[6], __int_as_float(s));
    } else {
#pragma unroll
        for (int k = 0; k < FE; k++) v[k] = 0.f;
    }
#pragma unroll
    for (int k = 0; k < FE; k++) {
        float x = v[k];
#pragma unroll
        for (int o = 16; o > 0; o >>= 1) x += __shfl_down_sync(0xffffffffu, x, o);
        if ((threadIdx.x & 31) == 0) atomicAdd(&sh[k], x);
    }
    __syncthreads();
    if (threadIdx.x < FE) atomicAdd(&g_eamean[threadIdx.x], sh[threadIdx.x]);
}

// ---- node transform for layers 2/3 (F=HC, BN+act fused) ----
__global__ void transform_kernel(int insel,
                                 const float* __restrict__ Wl, const float* __restrict__ bl,
                                 const float* __restrict__ Wr, const float* __restrict__ br,
                                 int n) {
    __shared__ float sWl[HC * HC], sWr[HC * HC], sb[2 * HC];
    for (int t = threadIdx.x; t < HC * HC; t += blockDim.x) { sWl[t] = Wl[t]; sWr[t] = Wr[t]; }
    for (int t = threadIdx.x; t < HC; t += blockDim.x) { sb[t] = bl[t]; sb[HC + t] = br[t]; }
    if (blockIdx.x == 0 && threadIdx.x < 2 * HC) g_stats[threadIdx.x] = 0.f;
    __syncthreads();
    int i = blockIdx.x * blockDim.x + threadIdx.x;
    if (i >= n) return;
    const float* hin = insel ? g_h2 : g_h1;

    float in[HC];
#pragma unroll
    for (int k = 0; k < HC; k++) {
        float v = hin[(size_t)i * HC + k];
        v = v * g_ab[k] + g_ab[HC + k];
        in[k] = lrelu(v, 0.01f);
    }
    float vl[HC], vr[HC];
#pragma unroll
    for (int c = 0; c < HC; c++) { vl[c] = sb[c]; vr[c] = sb[HC + c]; }
#pragma unroll
    for (int k = 0; k < HC; k++) {
        float a = in[k];
#pragma unroll
        for (int c = 0; c < HC; c++) { vl[c] += a * sWl[k * HC + c]; vr[c] += a * sWr[k * HC + c]; }
    }
    float4* pl = (float4*)(g_xl + (size_t)i * HC);
    float4* pr = (float4*)(g_xr + (size_t)i * HC);
#pragma unroll
    for (int q = 0; q < 8; q++) {
        pl[q] = make_float4(vl[q * 4], vl[q * 4 + 1], vl[q * 4 + 2], vl[q * 4 + 3]);
        pr[q] = make_float4(vr[q * 4], vr[q * 4 + 1], vr[q * 4 + 2], vr[q * 4 + 3]);
    }
}

// ---------------- warp-per-node GATv2: cp.async ring + f32x2 + 1-iter xl prefetch -------
// group g = lane>>3 owns one edge per iteration; cs = lane&7 owns channels [cs*4,cs*4+4).
// fill(j+2) issued BEFORE wait_group 1 -> rounds j and j+1 both resident while consuming
// round j; full rounds are unrolled x4 so the "next record" address is compile-time,
// and the next iteration's xl LDG is issued before computing the current one.
// Records clamped to rec 0 when OOB (pedge pad zeroed) -> all srcs valid, no addr selects.
template <int MODE>
__global__ void __launch_bounds__(256, 3)
gat_aggr_kernel(const float* __restrict__ We, const float* __restrict__ att,
                const float* __restrict__ bias, float invE, int n, int hsel,
                float* __restrict__ out) {
    __shared__ __align__(16) char ringbuf[8 * 3 * 512];  // 8 warps x 3 rounds x 512B
    __shared__ float sWem[HC];   // ee_mean = (mean ea) @ We
    __shared__ float sb[HC];
    __shared__ float swf[HC + 1];
    __shared__ float sst[2 * HC];
    int t = threadIdx.x;
    if (t < HC) {
        sb[t] = bias[t];
        float s = 0.f;
#pragma unroll
        for (int k = 0; k < FE; k++) s += g_eamean[k] * invE * We[k * HC + t];
        sWem[t] = s;
    }
    if (MODE == 0 && t < 2 * HC) sst[t] = 0.f;
    if (MODE == 1 && t < HC + 1) swf[t] = g_weff[t];
    __syncthreads();

    const unsigned FULL = 0xffffffffu;
    int lane = threadIdx.x & 31;
    int warpid = threadIdx.x >> 5;
    int g = lane >> 3, cs = lane & 7;

    uint64_t wk01[FE], wk23[FE];
#pragma unroll
    for (int k = 0; k < FE; k++) {
        float4 w = *(const float4*)(We + k * HC + cs * 4);
        PACK_F32X2(wk01[k], w.x, w.y);
        PACK_F32X2(wk23[k], w.z, w.w);
    }
    float4 att4 = *(const float4*)(att + cs * 4);

    int i = (blockIdx.x * blockDim.x + threadIdx.x) >> 5;
    if (i < n) {
        int r0 = g_rowptr[i];
        int deg = g_rowptr[i + 1] - r0;
        float4 xr4 = *(const float4*)(g_xr + (size_t)i * HC + cs * 4);
        uint64_t xr01, xr23;
        PACK_F32X2(xr01, xr4.x, xr4.y);
        PACK_F32X2(xr23, xr4.z, xr4.w);
        float4 acc = make_float4(0.f, 0.f, 0.f, 0.f);
        float den = 0.f;

        const char* peb = (const char*)g_pedge + (size_t)r0 * 32;
        char* ringw = ringbuf + warpid * 1536;
        uint32_t ru32 = smem_u32(ringw);

        int nit = (deg + 3) >> 2;       // iterations of 4 edges
        int nrounds = (nit + 3) >> 2;   // rounds of 16 records

        auto fill = [&](int j) {
            int r = j * 16 + (lane >> 1);
            int rc = (r < deg) ? r : 0;
            uint32_t dst = ru32 + (uint32_t)(j % 3) * 512u + (uint32_t)lane * 16u;
            CP_ASYNC16(dst, peb + (size_t)rc * 32 + (lane & 1) * 16);
            CP_COMMIT();
        };

        // per-edge compute: all operands in registers
        auto edge_compute = [&](float4 a0, float4 a1, float4 xl4, bool valid) {
            uint64_t e01 = xr01, e23 = xr23;
            uint64_t aa;
            PACK_F32X2(aa, a0.x, a0.x); FMA_F32X2(e01, aa, wk01[0], e01); FMA_F32X2(e23, aa, wk23[0], e23);
            PACK_F32X2(aa, a0.y, a0.y); FMA_F32X2(e01, aa, wk01[1], e01); FMA_F32X2(e23, aa, wk23[1], e23);
            PACK_F32X2(aa, a0.z, a0.z); FMA_F32X2(e01, aa, wk01[2], e01); FMA_F32X2(e23, aa, wk23[2], e23);
            PACK_F32X2(aa, a0.w, a0.w); FMA_F32X2(e01, aa, wk01[3], e01); FMA_F32X2(e23, aa, wk23[3], e23);
            PACK_F32X2(aa, a1.x, a1.x); FMA_F32X2(e01, aa, wk01[4], e01); FMA_F32X2(e23, aa, wk23[4], e23);
            PACK_F32X2(aa, a1.y, a1.y); FMA_F32X2(e01, aa, wk01[5], e01); FMA_F32X2(e23, aa, wk23[5], e23);
            PACK_F32X2(aa, a1.z, a1.z); FMA_F32X2(e01, aa, wk01[6], e01); FMA_F32X2(e23, aa, wk23[6], e23);
            float e0, e1, e2, e3;
            UNPACK_F32X2(e0, e1, e01);
            UNPACK_F32X2(e2, e3, e23);

            float m0 = lrelu(xl4.x + e0, 0.2f);
            float m1 = lrelu(xl4.y + e1, 0.2f);
            float m2 = lrelu(xl4.z + e2, 0.2f);
            float m3 = lrelu(xl4.w + e3, 0.2f);
            float pl = fmaf(m0, att4.x, fmaf(m1, att4.y, fmaf(m2, att4.z, m3 * att4.w)));
            float lg = pl + __shfl_xor_sync(FULL, pl, 1);
            float ex = valid ? __expf(lg) : 0.f;
            den += ex;
            acc.x = fmaf(ex, xl4.x, acc.x);
            acc.y = fmaf(ex, xl4.y, acc.y);
            acc.z = fmaf(ex, xl4.z, acc.z);
            acc.w = fmaf(ex, xl4.w, acc.w);
        };

        fill(0);
        fill(1);

        float4 xlN;
        for (int j = 0; j < nrounds; j++) {
            fill(j + 2);
            CP_WAIT1();             // rounds j and j+1 resident; only fill(j+2) pending
            __syncwarp();
            const char* slotb  = ringw + (j % 3) * 512 + (g << 5);
            const char* slotbN = ringw + ((j + 1) % 3) * 512 + (g << 5);
            int itb = j * 4;
            int rem = nit - itb;

            if (j == 0) {           // prologue: prefetch iteration 0's xl
                int s0 = __float_as_int(*(const float*)(slotb + 28));
                xlN = *(const float4*)(g_xl + (size_t)s0 * HC + cs * 4);
            }

            if (rem >= 4) {
#pragma unroll
                for (int tt = 0; tt < 4; tt++) {
                    const char* recp = slotb + (tt << 7);
                    float4 a0 = *(const float4*)recp;
                    float4 a1 = *(const float4*)(recp + 16);
                    float4 xl4 = xlN;
                    // prefetch next iteration's xl (compile-time record address)
                    const char* nrec = (tt < 3) ? (slotb + ((tt + 1) << 7)) : slotbN;
                    int sN = __float_as_int(*(const float*)(nrec + 28));
                    xlN = *(const float4*)(g_xl + (size_t)sN * HC + cs * 4);
                    bool valid = ((itb + tt) * 4 + g) < deg;
                    edge_compute(a0, a1, xl4, valid);
                }
            } else {
                for (int tt = 0; tt < rem; tt++) {
                    const char* recp = slotb + (tt << 7);
                    float4 a0 = *(const float4*)recp;
                    float4 a1 = *(const float4*)(recp + 16);
                    int s = __float_as_int(a1.w);
                    float4 xl4 = *(const float4*)(g_xl + (size_t)s * HC + cs * 4);
                    bool valid = ((itb + tt) * 4 + g) < deg;
                    edge_compute(a0, a1, xl4, valid);
                }
            }
        }

        // self-loop contribution (ea = mean): all lanes compute; group 0 accumulates
        {
            float4 xli = *(const float4*)(g_xl + (size_t)i * HC + cs * 4);
            float m0 = lrelu(xli.x + xr4.x + sWem[cs * 4 + 0], 0.2f);
            float m1 = lrelu(xli.y + xr4.y + sWem[cs * 4 + 1], 0.2f);
            float m2 = lrelu(xli.z + xr4.z + sWem[cs * 4 + 2], 0.2f);
            float m3 = lrelu(xli.w + xr4.w + sWem[cs * 4 + 3], 0.2f);
            float pl = fmaf(m0, att4.x, fmaf(m1, att4.y, fmaf(m2, att4.z, m3 * att4.w)));
            float lg = pl + __shfl_xor_sync(FULL, pl, 1);
            float ex = __expf(lg);
            if (g == 0) {
                den += ex;
                acc.x = fmaf(ex, xli.x, acc.x);
                acc.y = fmaf(ex, xli.y, acc.y);
                acc.z = fmaf(ex, xli.z, acc.z);
                acc.w = fmaf(ex, xli.w, acc.w);
            }
        }

#pragma unroll
        for (int off = 8; off < 32; off <<= 1) {
            acc.x += __shfl_xor_sync(FULL, acc.x, off);
            acc.y += __shfl_xor_sync(FULL, acc.y, off);
            acc.z += __shfl_xor_sync(FULL, acc.z, off);
            acc.w += __shfl_xor_sync(FULL, acc.w, off);
            den   += __shfl_xor_sync(FULL, den,   off);
        }
        if (g == 0) {
            float inv = 1.f / (den + 1e-16f);
            float h0 = acc.x * inv + sb[cs * 4];
            float h1 = acc.y * inv + sb[cs * 4 + 1];
            float h2 = acc.z * inv + sb[cs * 4 + 2];
            float h3 = acc.w * inv + sb[cs * 4 + 3];
            if (MODE == 0) {
                float* hp = (hsel ? g_h2 : g_h1) + (size_t)i * HC + cs * 4;
                *(float4*)hp = make_float4(h0, h1, h2, h3);
                atomicAdd(&sst[cs * 4 + 0], h0);
                atomicAdd(&sst[cs * 4 + 1], h1);
                atomicAdd(&sst[cs * 4 + 2], h2);
                atomicAdd(&sst[cs * 4 + 3], h3);
                atomicAdd(&sst[HC + cs * 4 + 0], h0 * h0);
                atomicAdd(&sst[HC + cs * 4 + 1], h1 * h1);
                atomicAdd(&sst[HC + cs * 4 + 2], h2 * h2);
                atomicAdd(&sst[HC + cs * 4 + 3], h3 * h3);
            } else {
                float s = lrelu(h0, 0.01f) * swf[cs * 4]
                        + lrelu(h1, 0.01f) * swf[cs * 4 + 1]
                        + lrelu(h2, 0.01f) * swf[cs * 4 + 2]
                        + lrelu(h3, 0.01f) * swf[cs * 4 + 3];
                s += __shfl_xor_sync(0x000000ffu, s, 1);
                s += __shfl_xor_sync(0x000000ffu, s, 2);
                s += __shfl_xor_sync(0x000000ffu, s, 4);
                if (cs == 0) out[i] = s + swf[HC];
            }
        }
    }
    if (MODE == 0) {
        __syncthreads();
        if (t < 2 * HC) atomicAdd(&g_stats[t], sst[t]);
    }
}

__global__ void bn_finalize_kernel(const float* __restrict__ gamma,
                                   const float* __restrict__ beta, float invn) {
    int c = threadIdx.x;
    if (c >= HC) return;
    float mu = g_stats[c] * invn;
    float var = g_stats[HC + c] * invn - mu * mu;
    float A = rsqrtf(var + 1e-5f) * gamma[c];
    g_ab[c] = A;
    g_ab[HC + c] = beta[c] - mu * A;
}

// ---------------- launch ----------------
extern "C" void kernel_launch(void* const* d_in, const int* in_sizes, int n_in,
                              void* d_out, int out_size) {
    const float* x    = (const float*)d_in[0];
    const int*   eidx = (const int*)d_in[1];
    const float* ea   = (const float*)d_in[2];
    const float* Wl1 = (const float*)d_in[3];  const float* bl1 = (const float*)d_in[4];
    const float* Wr1 = (const float*)d_in[5];  const float* br1 = (const float*)d_in[6];
    const float* We1 = (const float*)d_in[7];  const float* att1 = (const float*)d_in[8];
    const float* b1  = (const float*)d_in[9];
    const float* Wl2 = (const float*)d_in[10]; const float* bl2 = (const float*)d_in[11];
    const float* Wr2 = (const float*)d_in[12]; const float* br2 = (const float*)d_in[13];
    const float* We2 = (const float*)d_in[14]; const float* att2 = (const float*)d_in[15];
    const float* b2  = (const float*)d_in[16];
    const float* gamma = (const float*)d_in[17]; const float* beta = (const float*)d_in[18];
    const float* Wreg = (const float*)d_in[19];  const float* breg = (const float*)d_in[20];
    const float* Wend = (const float*)d_in[21];  const float* bend = (const float*)d_in[22];
    float* out = (float*)d_out;

    int n = in_sizes[0] / FN;
    int E = in_sizes[1] / 2;
    float invE = 1.f / (float)E;
    int nbN = (n + 255) / 256;
    int nbE = (E + 255) / 256;
    int nbW = (n * 32 + 255) / 256;

    t1_hist_kernel<<<nbN + nbE, 256>>>(x, Wl1, bl1, Wr1, br1, n, eidx, E, nbN); // 0
    scan_kernel<<<1, 1024>>>(n, Wreg, breg, Wend, bend);                        // 1
    scatter_kernel<<<nbE, 256>>>(eidx, ea, E);                                  // 2
    gat_aggr_kernel<0><<<nbW, 256>>>(We1, att1, b1, invE, n, 0, nullptr);       // 3 <- profiled
    bn_finalize_kernel<<<1, 32>>>(gamma, beta, 1.f / (float)n);                 // 4

    transform_kernel<<<nbN, 256>>>(0, Wl2, bl2, Wr2, br2, n);                   // 5
    gat_aggr_kernel<0><<<nbW, 256>>>(We2, att2, b2, invE, n, 1, nullptr);       // 6
    bn_finalize_kernel<<<1, 32>>>(gamma, beta, 1.f / (float)n);                 // 7

    transform_kernel<<<nbN, 256>>>(1, Wl2, bl2, Wr2, br2, n);                   // 8
    gat_aggr_kernel<1><<<nbW, 256>>>(We2, att2, b2, invE, n, 0, out);           // 9
}